// round 1
// baseline (speedup 1.0000x reference)
#include <cuda_runtime.h>
#include <cuda_bf16.h>

// Problem constants (reference: N=100000, E=1000000, D=64)
#define MAXN 100000
#define DIMF 64

// Scratch (device globals; no allocation allowed)
__device__ float g_agg[MAXN * DIMF];
__device__ float g_h1[MAXN * DIMF];
__device__ float g_h2[MAXN * DIMF];

// ---------------------------------------------------------------------------
// Zero kernel: clears agg (float4 stores)
// ---------------------------------------------------------------------------
__global__ void zero_kernel(float4* __restrict__ p, int n4) {
    int i = blockIdx.x * blockDim.x + threadIdx.x;
    if (i < n4) p[i] = make_float4(0.f, 0.f, 0.f, 0.f);
}

// ---------------------------------------------------------------------------
// Scatter: agg[dst] += x[src] * ew   (16 threads per edge, vector red.v4.f32)
// ---------------------------------------------------------------------------
__global__ void scatter_kernel(const float4* __restrict__ x4,
                               const int* __restrict__ src,
                               const int* __restrict__ dst,
                               const float* __restrict__ ew,
                               float* __restrict__ agg,
                               int E) {
    int idx = blockIdx.x * blockDim.x + threadIdx.x;
    int e = idx >> 4;
    if (e >= E) return;
    int c = idx & 15;
    int s = __ldg(src + e);
    int d = __ldg(dst + e);
    float w = __ldg(ew + e);
    float4 v = x4[(size_t)s * 16 + c];
    float rx = v.x * w, ry = v.y * w, rz = v.z * w, rw = v.w * w;
    float* p = agg + ((size_t)d * 64 + c * 4);
    asm volatile("red.global.add.v4.f32 [%0], {%1,%2,%3,%4};"
                 :: "l"(p), "f"(rx), "f"(ry), "f"(rz), "f"(rw) : "memory");
}

// ---------------------------------------------------------------------------
// Fused MLP: out = [relu]( relu((agg+xin) @ W1 + b1) @ W2 + b2 )
// 64 rows per block, 256 threads. Weights transposed in smem with padded
// strides so float4 loads are conflict-free. 8-row register blocking.
// ---------------------------------------------------------------------------
template<int H, bool RELU_OUT>
__global__ void __launch_bounds__(256) mlp_kernel(
        const float* __restrict__ agg, const float* __restrict__ xin,
        const float* __restrict__ w1, const float* __restrict__ b1,
        const float* __restrict__ w2, const float* __restrict__ b2,
        float* __restrict__ out, int N) {
    constexpr int TR  = 64;       // rows per block
    constexpr int W1S = 68;       // w1t row stride (words), 16B-aligned, conflict-free
    constexpr int W2S = H + 4;    // w2t row stride

    extern __shared__ float sm[];
    float* in_s = sm;                       // TR*64
    float* w1t  = in_s + TR * 64;           // H * W1S   (w1t[c][k] = w1[k*H+c])
    float* hid  = w1t + H * W1S;            // TR * H
    float* w2t  = hid + TR * H;             // 64 * W2S  (w2t[c][h] = w2[h*64+c])
    float* b1s  = w2t + 64 * W2S;           // H
    float* b2s  = b1s + H;                  // 64

    int tid  = threadIdx.x;
    int row0 = blockIdx.x * TR;
    int nrows = N - row0; if (nrows > TR) nrows = TR;

    // Load weights (transposed) + biases
    for (int i = tid; i < 64 * H; i += 256) {
        int k = i / H, c = i % H;
        w1t[c * W1S + k] = w1[i];
    }
    for (int i = tid; i < H * 64; i += 256) {
        int h = i / 64, c = i % 64;
        w2t[c * W2S + h] = w2[i];
    }
    if (tid < H)  b1s[tid] = b1[tid];
    if (tid < 64) b2s[tid] = b2[tid];

    // Load input tile: in = agg + xin (zero-pad tail rows)
    for (int i = tid; i < TR * 64; i += 256) {
        int r = i >> 6, k = i & 63;
        float v = 0.f;
        if (r < nrows) {
            size_t g = (size_t)(row0 + r) * 64 + k;
            v = agg[g] + xin[g];
        }
        in_s[i] = v;
    }
    __syncthreads();

    // GEMM1: hid[r][c] = relu(b1[c] + sum_k in[r][k] * w1t[c][k])
    {
        constexpr int GROUPS = 256 / H;          // 4 (H=64) or 2 (H=128)
        constexpr int RPT = 8;
        constexpr int PASS_ROWS = GROUPS * RPT;  // 32 or 16
        int c = tid % H;
        int g = tid / H;
        const float4* wrow = (const float4*)(w1t + c * W1S);
        float bv = b1s[c];
        for (int r0 = 0; r0 < TR; r0 += PASS_ROWS) {
            int rb = r0 + g * RPT;
            float acc[RPT];
            #pragma unroll
            for (int j = 0; j < RPT; j++) acc[j] = bv;
            #pragma unroll 8
            for (int k4 = 0; k4 < 16; k4++) {
                float4 wv = wrow[k4];
                #pragma unroll
                for (int j = 0; j < RPT; j++) {
                    float4 iv = ((const float4*)(in_s + (rb + j) * 64))[k4];
                    acc[j] += iv.x * wv.x + iv.y * wv.y + iv.z * wv.z + iv.w * wv.w;
                }
            }
            #pragma unroll
            for (int j = 0; j < RPT; j++)
                hid[(rb + j) * H + c] = fmaxf(acc[j], 0.f);
        }
    }
    __syncthreads();

    // GEMM2: out[r][c] = b2[c] + sum_h hid[r][h] * w2t[c][h]
    {
        constexpr int RPT = 16;       // 4 groups x 16 rows = 64 rows
        int c = tid & 63;
        int g = tid >> 6;             // 0..3
        int rb = g * RPT;
        const float4* wrow = (const float4*)(w2t + c * W2S);
        float bv = b2s[c];
        float acc[RPT];
        #pragma unroll
        for (int j = 0; j < RPT; j++) acc[j] = bv;
        #pragma unroll 8
        for (int h4 = 0; h4 < H / 4; h4++) {
            float4 wv = wrow[h4];
            #pragma unroll
            for (int j = 0; j < RPT; j++) {
                float4 hv = ((const float4*)(hid + (rb + j) * H))[h4];
                acc[j] += hv.x * wv.x + hv.y * wv.y + hv.z * wv.z + hv.w * wv.w;
            }
        }
        #pragma unroll
        for (int j = 0; j < RPT; j++) {
            int r = rb + j;
            if (r < nrows) {
                float v = acc[j];
                if (RELU_OUT) v = fmaxf(v, 0.f);
                out[(size_t)(row0 + r) * 64 + c] = v;
            }
        }
    }
}

// ---------------------------------------------------------------------------
// Launch
// ---------------------------------------------------------------------------
static inline size_t mlp_smem(int H) {
    return (size_t)(64 * 64 + H * 68 + 64 * H + 64 * (H + 4) + H + 64) * sizeof(float);
}

extern "C" void kernel_launch(void* const* d_in, const int* in_sizes, int n_in,
                              void* d_out, int out_size) {
    const float* x   = (const float*)d_in[0];
    const int*   ei  = (const int*)d_in[1];
    const float* ew  = (const float*)d_in[2];
    const float* w11 = (const float*)d_in[3];
    const float* b11 = (const float*)d_in[4];
    const float* w12 = (const float*)d_in[5];
    const float* b12 = (const float*)d_in[6];
    const float* w21 = (const float*)d_in[7];
    const float* b21 = (const float*)d_in[8];
    const float* w22 = (const float*)d_in[9];
    const float* b22 = (const float*)d_in[10];
    const float* w31 = (const float*)d_in[11];
    const float* b31 = (const float*)d_in[12];
    const float* w32 = (const float*)d_in[13];
    const float* b32 = (const float*)d_in[14];
    float* out = (float*)d_out;

    int N = in_sizes[0] / DIMF;
    int E = in_sizes[1] / 2;
    const int* src = ei;
    const int* dst = ei + E;

    float *agg, *h1, *h2;
    cudaGetSymbolAddress((void**)&agg, g_agg);
    cudaGetSymbolAddress((void**)&h1, g_h1);
    cudaGetSymbolAddress((void**)&h2, g_h2);

    size_t sm64  = mlp_smem(64);
    size_t sm128 = mlp_smem(128);
    cudaFuncSetAttribute(mlp_kernel<64, true>,  cudaFuncAttributeMaxDynamicSharedMemorySize, (int)sm64);
    cudaFuncSetAttribute(mlp_kernel<128, true>, cudaFuncAttributeMaxDynamicSharedMemorySize, (int)sm128);
    cudaFuncSetAttribute(mlp_kernel<64, false>, cudaFuncAttributeMaxDynamicSharedMemorySize, (int)sm64);

    int n4 = N * 16;                         // float4 count of agg
    int zb = (n4 + 255) / 256;
    int sb = (E * 16 + 255) / 256;
    int mb = (N + 63) / 64;

    // Layer 1: 64 -> 64 -> 64, relu
    zero_kernel<<<zb, 256>>>((float4*)agg, n4);
    scatter_kernel<<<sb, 256>>>((const float4*)x, src, dst, ew, agg, E);
    mlp_kernel<64, true><<<mb, 256, sm64>>>(agg, x, w11, b11, w12, b12, h1, N);

    // Layer 2: 64 -> 128 -> 64, relu
    zero_kernel<<<zb, 256>>>((float4*)agg, n4);
    scatter_kernel<<<sb, 256>>>((const float4*)h1, src, dst, ew, agg, E);
    mlp_kernel<128, true><<<mb, 256, sm128>>>(agg, h1, w21, b21, w22, b22, h2, N);

    // Layer 3: 64 -> 64 -> 64, no relu
    zero_kernel<<<zb, 256>>>((float4*)agg, n4);
    scatter_kernel<<<sb, 256>>>((const float4*)h2, src, dst, ew, agg, E);
    mlp_kernel<64, false><<<mb, 256, sm64>>>(agg, h2, w31, b31, w32, b32, out, N);
}